// round 15
// baseline (speedup 1.0000x reference)
#include <cuda_runtime.h>
#include <cuda_bf16.h>
#include <cstdint>

#define Ss 1024
#define Ee 1024
#define Hh 16
#define Dd 64
#define BH 64
#define Mm 4096
#define SB 40            // smem stride bf16 for 32-col tiles (+8 pad) — ldmatrix conflict-free
#define SQ 72            // smem stride bf16 for 64-col tiles (+8 pad) — ldmatrix conflict-free
#define SCALE 0.03125f

typedef __nv_bfloat16 bf16;

// ----------------- scratch -----------------
__device__ bf16 g_xh[Mm * Ee],      g_xl[Mm * Ee];
__device__ bf16 g_Wqkh[Hh * 128 * Ee], g_Wqkl[Hh * 128 * Ee];
__device__ bf16 g_Woh[Ee * Ee],     g_Wol[Ee * Ee];
__device__ bf16 g_Qh[BH * Ss * Dd], g_Ql[BH * Ss * Dd];
__device__ bf16 g_Kh[BH * Ss * Dd], g_Kl[BH * Ss * Dd];
__device__ bf16 g_VTh[BH * Dd * Ss], g_VTl[BH * Dd * Ss];
__device__ bf16 g_AOh[Mm * Ee],     g_AOl[Mm * Ee];
__device__ float g_rZ[BH * Ss];

// ----------------- helpers -----------------
__device__ __forceinline__ uint32_t smem_u32(const void* p) {
    uint32_t a;
    asm("{ .reg .u64 t; cvta.to.shared.u64 t, %1; cvt.u32.u64 %0, t; }" : "=r"(a) : "l"(p));
    return a;
}
__device__ __forceinline__ uint32_t pk2f(float a, float b) {
    bf16 x = __float2bfloat16(a), y = __float2bfloat16(b);
    return (uint32_t)*(uint16_t*)&x | ((uint32_t)*(uint16_t*)&y << 16);
}
__device__ __forceinline__ void splitst(bf16* hp, bf16* lp, float4 v) {
    bf16 hx = __float2bfloat16(v.x), hy = __float2bfloat16(v.y);
    bf16 hz = __float2bfloat16(v.z), hw = __float2bfloat16(v.w);
    *(uint32_t*)hp       = (uint32_t)*(uint16_t*)&hx | ((uint32_t)*(uint16_t*)&hy << 16);
    *(uint32_t*)(hp + 2) = (uint32_t)*(uint16_t*)&hz | ((uint32_t)*(uint16_t*)&hw << 16);
    *(uint32_t*)lp       = pk2f(v.x - __bfloat162float(hx), v.y - __bfloat162float(hy));
    *(uint32_t*)(lp + 2) = pk2f(v.z - __bfloat162float(hz), v.w - __bfloat162float(hw));
}
__device__ __forceinline__ void wr_split(bf16* oh, bf16* ol, size_t idx, float a, float b) {
    bf16 ha = __float2bfloat16(a), hb = __float2bfloat16(b);
    *(uint32_t*)(oh + idx) = (uint32_t)*(uint16_t*)&ha | ((uint32_t)*(uint16_t*)&hb << 16);
    *(uint32_t*)(ol + idx) = pk2f(a - __bfloat162float(ha), b - __bfloat162float(hb));
}
__device__ __forceinline__ void mma16816(float* c, const uint32_t a[4], uint32_t b0, uint32_t b1) {
    asm volatile("mma.sync.aligned.m16n8k16.row.col.f32.bf16.bf16.f32 "
                 "{%0,%1,%2,%3}, {%4,%5,%6,%7}, {%8,%9}, {%0,%1,%2,%3};"
                 : "+f"(c[0]), "+f"(c[1]), "+f"(c[2]), "+f"(c[3])
                 : "r"(a[0]), "r"(a[1]), "r"(a[2]), "r"(a[3]), "r"(b0), "r"(b1));
}
__device__ __forceinline__ void ldsm4(uint32_t addr, uint32_t* r) {
    asm volatile("ldmatrix.sync.aligned.m8n8.x4.shared.b16 {%0,%1,%2,%3}, [%4];"
                 : "=r"(r[0]), "=r"(r[1]), "=r"(r[2]), "=r"(r[3]) : "r"(addr));
}
__device__ __forceinline__ void cpasync16(uint32_t dst, const void* src) {
    asm volatile("cp.async.cg.shared.global [%0], [%1], 16;" :: "r"(dst), "l"(src));
}
__device__ __forceinline__ void cp_commit() { asm volatile("cp.async.commit_group;" ::: "memory"); }
template<int N> __device__ __forceinline__ void cp_wait() {
    asm volatile("cp.async.wait_group %0;" :: "n"(N) : "memory");
}
// ROWS x 32 bf16 (64B rows), stride SB.  256 threads.
template<int ROWS>
__device__ __forceinline__ void cp_r32(uint32_t sdst, const bf16* g, size_t ld, int t) {
#pragma unroll
    for (int i = 0; i < ROWS * 4 / 256; i++) {
        int c = i * 256 + t, row = c >> 2, cid = c & 3;
        cpasync16(sdst + row * (SB * 2) + cid * 16, g + (size_t)row * ld + cid * 8);
    }
}
// ROWS x 64 bf16 (128B rows), stride SQ.  256 threads.
template<int ROWS>
__device__ __forceinline__ void cp_r64(uint32_t sdst, const bf16* g, size_t ld, int t) {
#pragma unroll
    for (int i = 0; i < ROWS * 8 / 256; i++) {
        int c = i * 256 + t, row = c >> 3, cid = c & 7;
        cpasync16(sdst + row * (SQ * 2) + cid * 16, g + (size_t)row * ld + cid * 8);
    }
}
// 3-term split-bf16 tile MMA with ldmatrix fragment loads.
template<int SA_, int SBB, int MT, int NT, int KK>
__device__ __forceinline__ void mma_tile(uint32_t aH, uint32_t aL,
    uint32_t bH, uint32_t bL, int wm, int wn, int lane, float (*acc)[NT][4])
{
    const int ar  = (wm + (lane & 15)) * SA_ + ((lane >> 4) << 3);
    const int br0 = (wn + (lane & 7) + ((lane >> 4) << 3)) * SBB + (((lane >> 3) & 1) << 3);
#pragma unroll
    for (int ks = 0; ks < KK; ks += 16) {
        uint32_t ah[MT][4], al[MT][4];
#pragma unroll
        for (int mt = 0; mt < MT; mt++) {
            ldsm4(aH + (uint32_t)(ar + mt * 16 * SA_ + ks) * 2, ah[mt]);
            ldsm4(aL + (uint32_t)(ar + mt * 16 * SA_ + ks) * 2, al[mt]);
        }
        uint32_t bhv[NT][2], blv[NT][2];
#pragma unroll
        for (int np = 0; np < NT / 2; np++) {
            uint32_t r[4];
            ldsm4(bH + (uint32_t)(br0 + np * 16 * SBB + ks) * 2, r);
            bhv[2*np][0] = r[0]; bhv[2*np][1] = r[1];
            bhv[2*np+1][0] = r[2]; bhv[2*np+1][1] = r[3];
            ldsm4(bL + (uint32_t)(br0 + np * 16 * SBB + ks) * 2, r);
            blv[2*np][0] = r[0]; blv[2*np][1] = r[1];
            blv[2*np+1][0] = r[2]; blv[2*np+1][1] = r[3];
        }
#pragma unroll
        for (int nt = 0; nt < NT; nt++)
#pragma unroll
            for (int mt = 0; mt < MT; mt++) {
                mma16816(acc[mt][nt], ah[mt], bhv[nt][0], bhv[nt][1]);
                mma16816(acc[mt][nt], ah[mt], blv[nt][0], blv[nt][1]);
                mma16816(acc[mt][nt], al[mt], bhv[nt][0], bhv[nt][1]);
            }
    }
}

// ----------------- conversion / transpose kernels -----------------
__global__ void k_cvtx(const float* __restrict__ x) {
    int idx = blockIdx.x * 256 + threadIdx.x;
    float4 v = ((const float4*)x)[idx];
    splitst(g_xh + idx * 4, g_xl + idx * 4, v);
}
__global__ void k_trwf(const float* __restrict__ in, bf16* __restrict__ oh, bf16* __restrict__ ol,
                       int R, int C, size_t islab, size_t oslab, int row_off)
{
    __shared__ float tile[32][33];
    const float* I = in + (size_t)blockIdx.z * islab;
    int r0 = blockIdx.x << 5, c0 = blockIdx.y << 5;
    int tx = threadIdx.x, ty = threadIdx.y;
#pragma unroll
    for (int i = ty; i < 32; i += 8)
        tile[i][tx] = I[(size_t)(r0 + i) * C + c0 + tx];
    __syncthreads();
#pragma unroll
    for (int i = ty; i < 32; i += 8) {
        float v = tile[tx][i];
        bf16 h = __float2bfloat16(v);
        size_t o = (size_t)blockIdx.z * oslab + (size_t)(row_off + c0 + i) * R + r0 + tx;
        oh[o] = h;
        ol[o] = __float2bfloat16(v - __bfloat162float(h));
    }
}
// fused: VT[bh][d][s] = Q[bh][s][d] * rZ[bh][s], split hi/lo.  Runs AFTER k_stats.
__global__ void k_trqs()
{
    __shared__ bf16 th[32][33], tl[32][33];
    int bh = blockIdx.z, s0 = blockIdx.x << 5, d0 = blockIdx.y << 5;
    int tx = threadIdx.x, ty = threadIdx.y;
    const bf16* Ih = g_Qh + (size_t)bh * Ss * Dd;
    const bf16* Il = g_Ql + (size_t)bh * Ss * Dd;
#pragma unroll
    for (int i = ty; i < 32; i += 8) {
        th[i][tx] = Ih[(size_t)(s0 + i) * Dd + d0 + tx];
        tl[i][tx] = Il[(size_t)(s0 + i) * Dd + d0 + tx];
    }
    __syncthreads();
    float rz = g_rZ[bh * Ss + s0 + tx];
#pragma unroll
    for (int i = ty; i < 32; i += 8) {
        float v = (__bfloat162float(th[tx][i]) + __bfloat162float(tl[tx][i])) * rz;
        bf16 h = __float2bfloat16(v);
        size_t o = (size_t)bh * Dd * Ss + (size_t)(d0 + i) * Ss + s0 + tx;
        g_VTh[o] = h;
        g_VTl[o] = __float2bfloat16(v - __bfloat162float(h));
    }
}

// ============================================================================
// k_proj: 128m x 64n tile of [Q|K] = x @ Wqk^T + bias.  grid (32,32), 256 thr.
// Single sync per chunk: wait -> sync -> issue-next -> mma.
// ============================================================================
__global__ __launch_bounds__(256, 3) void k_proj(const float* __restrict__ bq,
                                                 const float* __restrict__ bk)
{
    extern __shared__ char sm[];
    const int t = threadIdx.x, lane = t & 31, wid = t >> 5;
    const int wm = (wid >> 1) * 32, wn = (wid & 1) * 32;
    const int m0 = blockIdx.x << 7, h = blockIdx.y >> 1, nh = blockIdx.y & 1;
    uint32_t sb = smem_u32(sm);
    const bf16* Ahg = g_xh + (size_t)m0 * Ee;
    const bf16* Alg = g_xl + (size_t)m0 * Ee;
    const bf16* Bhg = g_Wqkh + ((size_t)h * 128 + nh * 64) * Ee;
    const bf16* Blg = g_Wqkl + ((size_t)h * 128 + nh * 64) * Ee;

    float acc[2][4][4];
#pragma unroll
    for (int i = 0; i < 2; i++)
#pragma unroll
        for (int j = 0; j < 4; j++)
#pragma unroll
            for (int v = 0; v < 4; v++) acc[i][j][v] = 0.f;

    cp_r32<128>(sb + 0,     Ahg, Ee, t);
    cp_r32<128>(sb + 10240, Alg, Ee, t);
    cp_r32<64> (sb + 20480, Bhg, Ee, t);
    cp_r32<64> (sb + 25600, Blg, Ee, t);
    cp_commit();
    for (int c = 0; c < 32; c++) {
        cp_wait<0>();
        __syncthreads();
        if (c < 31) {
            int k0 = (c + 1) * 32;
            uint32_t nb = sb + ((c + 1) & 1) * 30720u;
            cp_r32<128>(nb + 0,     Ahg + k0, Ee, t);
            cp_r32<128>(nb + 10240, Alg + k0, Ee, t);
            cp_r32<64> (nb + 20480, Bhg + k0, Ee, t);
            cp_r32<64> (nb + 25600, Blg + k0, Ee, t);
            cp_commit();
        }
        uint32_t ab = sb + (c & 1) * 30720u;
        mma_tile<SB, SB, 2, 4, 32>(ab, ab + 10240, ab + 20480, ab + 25600, wm, wn, lane, acc);
    }

    const int b = m0 >> 10, hb = b * Hh + h;
    const bool isQ = (nh == 0);
    bf16* dh = isQ ? g_Qh : g_Kh;
    bf16* dl = isQ ? g_Ql : g_Kl;
    const float* bias = (isQ ? bq : bk) + h * Dd;
    const int gr = lane >> 2, tc = (lane & 3) * 2;
#pragma unroll
    for (int mt = 0; mt < 2; mt++)
#pragma unroll
        for (int nt = 0; nt < 4; nt++) {
            int d = wn + nt * 8 + tc;
            float bx = bias[d], by = bias[d + 1];
            int s = (m0 & 1023) + wm + mt * 16 + gr;
            wr_split(dh, dl, ((size_t)hb * Ss + s) * Dd + d,
                     acc[mt][nt][0] + bx, acc[mt][nt][1] + by);
            wr_split(dh, dl, ((size_t)hb * Ss + s + 8) * Dd + d,
                     acc[mt][nt][2] + bx, acc[mt][nt][3] + by);
        }
}

// ============================================================================
// k_stats: Z[k] = sum_q exp(S_qk), S = QK^T/32.  grid (16 k-tiles, 64 bh).
// Single sync per chunk.
// ============================================================================
__global__ __launch_bounds__(256, 2) void k_stats()
{
    extern __shared__ char sm[];
    const int t = threadIdx.x, lane = t & 31, wid = t >> 5;
    const int wm = (wid >> 1) * 32, wn = (wid & 1) * 32;
    const int k0 = blockIdx.x << 6, bh = blockIdx.y;
    const int tc = (lane & 3) * 2;
    uint32_t sb = smem_u32(sm);
    const bf16* Qhg = g_Qh + (size_t)bh * Ss * Dd;
    const bf16* Qlg = g_Ql + (size_t)bh * Ss * Dd;

    cp_r64<64>(sb + 73728, g_Kh + ((size_t)bh * Ss + k0) * Dd, Dd, t);
    cp_r64<64>(sb + 82944, g_Kl + ((size_t)bh * Ss + k0) * Dd, Dd, t);
    cp_r64<128>(sb + 0,     Qhg, Dd, t);
    cp_r64<128>(sb + 18432, Qlg, Dd, t);
    cp_commit();

    float zs[4][2];
#pragma unroll
    for (int i = 0; i < 4; i++) { zs[i][0] = 0.f; zs[i][1] = 0.f; }

    for (int c = 0; c < 8; c++) {
        cp_wait<0>();
        __syncthreads();
        if (c < 7) {
            size_t q1 = (size_t)(c + 1) * 128;
            uint32_t nb = sb + ((c + 1) & 1) * 36864u;
            cp_r64<128>(nb + 0,     Qhg + q1 * Dd, Dd, t);
            cp_r64<128>(nb + 18432, Qlg + q1 * Dd, Dd, t);
            cp_commit();
        }
        float acc[2][4][4];
#pragma unroll
        for (int i = 0; i < 2; i++)
#pragma unroll
            for (int j = 0; j < 4; j++)
#pragma unroll
                for (int v = 0; v < 4; v++) acc[i][j][v] = 0.f;
        uint32_t ab = sb + (c & 1) * 36864u;
        mma_tile<SQ, SQ, 2, 4, 64>(ab, ab + 18432, sb + 73728, sb + 82944, wm, wn, lane, acc);
#pragma unroll
        for (int mt = 0; mt < 2; mt++)
#pragma unroll
            for (int nt = 0; nt < 4; nt++) {
                zs[nt][0] += __expf(acc[mt][nt][0] * SCALE) + __expf(acc[mt][nt][2] * SCALE);
                zs[nt][1] += __expf(acc[mt][nt][1] * SCALE) + __expf(acc[mt][nt][3] * SCALE);
            }
    }
#pragma unroll
    for (int nt = 0; nt < 4; nt++)
#pragma unroll
        for (int j = 0; j < 2; j++)
#pragma unroll
            for (int o = 4; o <= 16; o <<= 1) {
                zs[nt][j] += __shfl_xor_sync(0xFFFFFFFFu, zs[nt][j], o);
            }
    float* rz = (float*)(sm + 92160);
    __syncthreads();
    if (lane < 4) {
        int qw = wid >> 1;
#pragma unroll
        for (int nt = 0; nt < 4; nt++) {
            int col = wn + nt * 8 + tc;
            rz[qw * 64 + col]     = zs[nt][0];
            rz[qw * 64 + col + 1] = zs[nt][1];
        }
    }
    __syncthreads();
    if (t < 64) {
        float Z = rz[t] + rz[64 + t] + rz[128 + t] + rz[192 + t];
        g_rZ[bh * Ss + k0 + t] = 1.0f / Z;
    }
}

// ============================================================================
// k_avf: fused AO = exp(QK^T/32) @ (rZ⊙V).  grid (8, 64), 256 thr.
// smem map (99328 B total):
//   [0, 36864)      Q prologue (hi 18432 | lo 18432), dead after fragment hoist
//   [0, 40960)      P double buffer after hoist: pb*20480 {hi 10240 | lo 10240}
//   [40960, 68608)  K 3 stages: 40960 + s*9216 {hi 4608 | lo 4608}
//   [68608, 99328)  V 3 stages: 68608 + s*10240 {hi 5120 | lo 5120}
// ============================================================================
__global__ __launch_bounds__(256, 2) void k_avf()
{
    extern __shared__ char sm[];
    const int t = threadIdx.x, lane = t & 31, wid = t >> 5;
    const int wm1 = wid * 16;
    const int wm2 = (wid >> 1) * 32, wn2 = (wid & 1) * 32;
    const int q0 = blockIdx.x << 7, bh = blockIdx.y;
    const int gr = lane >> 2, tc = (lane & 3) * 2;
    uint32_t sb = smem_u32(sm);
    const bf16* Khg = g_Kh + (size_t)bh * Ss * Dd;
    const bf16* Klg = g_Kl + (size_t)bh * Ss * Dd;
    const bf16* Vhg = g_VTh + (size_t)bh * Dd * Ss;
    const bf16* Vlg = g_VTl + (size_t)bh * Dd * Ss;

    cp_r64<128>(sb + 0,     g_Qh + ((size_t)bh * Ss + q0) * Dd, Dd, t);
    cp_r64<128>(sb + 18432, g_Ql + ((size_t)bh * Ss + q0) * Dd, Dd, t);
    cp_r64<32>(sb + 40960, Khg, Dd, t);
    cp_r64<32>(sb + 45568, Klg, Dd, t);
    cp_r32<64>(sb + 68608, Vhg, Ss, t);
    cp_r32<64>(sb + 73728, Vlg, Ss, t);
    cp_commit();

    float acc2[2][4][4];
#pragma unroll
    for (int i = 0; i < 2; i++)
#pragma unroll
        for (int j = 0; j < 4; j++)
#pragma unroll
            for (int v = 0; v < 4; v++) acc2[i][j][v] = 0.f;

    const int ar1 = (wm1 + (lane & 15)) * SQ + ((lane >> 4) << 3);
    const int br1 = ((lane & 7) + ((lane >> 4) << 3)) * SQ + (((lane >> 3) & 1) << 3);
    uint32_t qh[4][4], ql[4][4];

    for (int c = 0; c < 32; c++) {
        int st = c % 3;
        if (c < 31) {
            int k1 = (c + 1) * 32, sn = (c + 1) % 3;
            uint32_t kb = sb + 40960 + sn * 9216u;
            uint32_t vb = sb + 68608 + sn * 10240u;
            cp_r64<32>(kb,        Khg + (size_t)k1 * Dd, Dd, t);
            cp_r64<32>(kb + 4608, Klg + (size_t)k1 * Dd, Dd, t);
            cp_r32<64>(vb,        Vhg + k1, Ss, t);
            cp_r32<64>(vb + 5120, Vlg + k1, Ss, t);
            cp_commit();
            cp_wait<1>();
        } else cp_wait<0>();
        __syncthreads();
        if (c == 0) {   // hoist Q fragments (chunk-invariant); Q smem dead afterwards
#pragma unroll
            for (int i = 0; i < 4; i++) {
                ldsm4(sb + (uint32_t)(ar1 + i * 16) * 2, qh[i]);
                ldsm4(sb + 18432 + (uint32_t)(ar1 + i * 16) * 2, ql[i]);
            }
            __syncthreads();   // no warp may write P (aliased over Q) before all preload
        }
        // MMA#1: S chunk (128q x 32k), warp tile 16q x 32k, Q from registers
        float acc1[4][4];
#pragma unroll
        for (int j = 0; j < 4; j++)
#pragma unroll
            for (int v = 0; v < 4; v++) acc1[j][v] = 0.f;
        uint32_t kb2 = sb + 40960 + st * 9216u;
#pragma unroll
        for (int i = 0; i < 4; i++) {
            int ks = i * 16;
            uint32_t bhv[4][2], blv[4][2];
#pragma unroll
            for (int np = 0; np < 2; np++) {
                uint32_t r[4];
                ldsm4(kb2 + (uint32_t)(br1 + np * 16 * SQ + ks) * 2, r);
                bhv[2*np][0] = r[0]; bhv[2*np][1] = r[1];
                bhv[2*np+1][0] = r[2]; bhv[2*np+1][1] = r[3];
                ldsm4(kb2 + 4608 + (uint32_t)(br1 + np * 16 * SQ + ks) * 2, r);
                blv[2*np][0] = r[0]; blv[2*np][1] = r[1];
                blv[2*np+1][0] = r[2]; blv[2*np+1][1] = r[3];
            }
#pragma unroll
            for (int nt = 0; nt < 4; nt++) {
                mma16816(acc1[nt], qh[i], bhv[nt][0], bhv[nt][1]);
                mma16816(acc1[nt], qh[i], blv[nt][0], blv[nt][1]);
                mma16816(acc1[nt], ql[i], bhv[nt][0], bhv[nt][1]);
            }
        }
        // exp + split -> P[pb]  (rZ already folded into V)
        int pb = c & 1;
        bf16* Ph = (bf16*)(sm + pb * 20480);
        bf16* Pl = (bf16*)(sm + pb * 20480 + 10240);
#pragma unroll
        for (int nt = 0; nt < 4; nt++) {
            int col = nt * 8 + tc;
            float p0 = __expf(acc1[nt][0] * SCALE);
            float p1 = __expf(acc1[nt][1] * SCALE);
            float p2 = __expf(acc1[nt][2] * SCALE);
            float p3 = __expf(acc1[nt][3] * SCALE);
            wr_split(Ph, Pl, (size_t)(wm1 + gr) * SB + col, p0, p1);
            wr_split(Ph, Pl, (size_t)(wm1 + gr + 8) * SB + col, p2, p3);
        }
        __syncthreads();
        // MMA#2: acc2 += P @ V'  (warp tile 32q x 32d); no trailing sync (P double-buffered,
        // K/V triple-buffered => next chunk's writes never touch buffers still being read)
        uint32_t vb2 = sb + 68608 + st * 10240u;
        mma_tile<SB, SB, 2, 4, 32>(sb + pb * 20480u, sb + pb * 20480u + 10240, vb2, vb2 + 5120,
                                   wm2, wn2, lane, acc2);
    }

    const int b = bh >> 4, h = bh & 15;
#pragma unroll
    for (int mt = 0; mt < 2; mt++)
#pragma unroll
        for (int nt = 0; nt < 4; nt++) {
            int q = q0 + wm2 + mt * 16 + gr, d = wn2 + nt * 8 + tc;
            wr_split(g_AOh, g_AOl, ((size_t)b * Ss + q) * Ee + h * Dd + d,
                     acc2[mt][nt][0], acc2[mt][nt][1]);
            wr_split(g_AOh, g_AOl, ((size_t)b * Ss + q + 8) * Ee + h * Dd + d,
                     acc2[mt][nt][2], acc2[mt][nt][3]);
        }
}

// ============================================================================
// k_oproj: out(128m x 64n) = AO @ Wo + bo.  grid (32, 16), 256 thr.
// Single sync per chunk.
// ============================================================================
__global__ __launch_bounds__(256, 3) void k_oproj(const float* __restrict__ bo,
                                                  float* __restrict__ out)
{
    extern __shared__ char sm[];
    const int t = threadIdx.x, lane = t & 31, wid = t >> 5;
    const int wm = (wid >> 1) * 32, wn = (wid & 1) * 32;
    const int m0 = blockIdx.x << 7, n0 = blockIdx.y << 6;
    uint32_t sb = smem_u32(sm);
    const bf16* Ahg = g_AOh + (size_t)m0 * Ee;
    const bf16* Alg = g_AOl + (size_t)m0 * Ee;
    const bf16* Bhg = g_Woh + (size_t)n0 * Ee;
    const bf16* Blg = g_Wol + (size_t)n0 * Ee;

    float acc[2][4][4];
#pragma unroll
    for (int i = 0; i < 2; i++)
#pragma unroll
        for (int j = 0; j < 4; j++)
#pragma unroll
            for (int v = 0; v < 4; v++) acc[i][j][v] = 0.f;

    cp_r32<128>(sb + 0,     Ahg, Ee, t);
    cp_r32<128>(sb + 10240, Alg, Ee, t);
    cp_r32<64> (sb + 20480, Bhg, Ee, t);
    cp_r32<64> (sb + 25600, Blg, Ee, t);
    cp_commit();
    for (int c = 0; c < 32; c++) {
        cp_wait<0>();
        __syncthreads();
        if (c < 31) {
            int k0 = (c + 1) * 32;
            uint32_t nb = sb + ((c + 1) & 1) * 30720u;
            cp_r32<128>(nb + 0,     Ahg + k0, Ee, t);
            cp_r32<128>(nb + 10240, Alg + k0, Ee, t);
            cp_r32<64> (nb + 20480, Bhg + k0, Ee, t);
            cp_r32<64> (nb + 25600, Blg + k0, Ee, t);
            cp_commit();
        }
        uint32_t ab = sb + (c & 1) * 30720u;
        mma_tile<SB, SB, 2, 4, 32>(ab, ab + 10240, ab + 20480, ab + 25600, wm, wn, lane, acc);
    }

    const int gr = lane >> 2, tc = (lane & 3) * 2;
#pragma unroll
    for (int mt = 0; mt < 2; mt++)
#pragma unroll
        for (int nt = 0; nt < 4; nt++) {
            int m = m0 + wm + mt * 16 + gr, n = n0 + wn + nt * 8 + tc;
            float bx = bo[n], by = bo[n + 1];
            *(float2*)(out + (size_t)m * Ee + n) =
                make_float2(acc[mt][nt][0] + bx, acc[mt][nt][1] + by);
            *(float2*)(out + (size_t)(m + 8) * Ee + n) =
                make_float2(acc[mt][nt][2] + bx, acc[mt][nt][3] + by);
        }
}

// ============================================================================
extern "C" void kernel_launch(void* const* d_in, const int* in_sizes, int n_in,
                              void* d_out, int out_size)
{
    const float* x  = (const float*)d_in[0];
    const float* Wq = (const float*)d_in[1];
    const float* bq = (const float*)d_in[2];
    const float* Wk = (const float*)d_in[3];
    const float* bk = (const float*)d_in[4];
    // d_in[5], d_in[6] (W_v, b_v) intentionally unused: reference bug v = q
    const float* Wo = (const float*)d_in[7];
    const float* bo = (const float*)d_in[8];
    float* out = (float*)d_out;

    cudaFuncSetAttribute(k_proj,  cudaFuncAttributeMaxDynamicSharedMemorySize, 61440);
    cudaFuncSetAttribute(k_stats, cudaFuncAttributeMaxDynamicSharedMemorySize, 93184);
    cudaFuncSetAttribute(k_avf,   cudaFuncAttributeMaxDynamicSharedMemorySize, 99328);
    cudaFuncSetAttribute(k_oproj, cudaFuncAttributeMaxDynamicSharedMemorySize, 61440);

    bf16 *Wqkh, *Wqkl, *Woh, *Wol;
    cudaGetSymbolAddress((void**)&Wqkh, g_Wqkh);
    cudaGetSymbolAddress((void**)&Wqkl, g_Wqkl);
    cudaGetSymbolAddress((void**)&Woh,  g_Woh);
    cudaGetSymbolAddress((void**)&Wol,  g_Wol);

    dim3 tb8(32, 8);
    k_cvtx<<<4096, 256>>>(x);
    k_trwf<<<dim3(32, 2, 16), tb8>>>(Wq, Wqkh, Wqkl, Ee, Dd, (size_t)Ee * Dd, 128 * Ee, 0);
    k_trwf<<<dim3(32, 2, 16), tb8>>>(Wk, Wqkh, Wqkl, Ee, Dd, (size_t)Ee * Dd, 128 * Ee, 64);
    k_trwf<<<dim3(32, 32, 1), tb8>>>(Wo, Woh, Wol, Ee, Ee, (size_t)Ee * Ee, (size_t)Ee * Ee, 0);

    k_proj <<<dim3(Mm / 128, Hh * 2), 256, 61440>>>(bq, bk);
    k_stats<<<dim3(Ss / 64, BH), 256, 93184>>>();
    k_trqs <<<dim3(32, 2, BH), tb8>>>();
    k_avf  <<<dim3(Ss / 128, BH), 256, 99328>>>();
    k_oproj<<<dim3(Mm / 128, Ee / 64), 256, 61440>>>(bo, out);
}

// round 16
// speedup vs baseline: 1.0770x; 1.0770x over previous
#include <cuda_runtime.h>
#include <cuda_bf16.h>
#include <cstdint>

#define Ss 1024
#define Ee 1024
#define Hh 16
#define Dd 64
#define BH 64
#define Mm 4096
#define SB 40            // smem stride bf16 for 32-col tiles (+8 pad) — ldmatrix conflict-free
#define SQ 72            // smem stride bf16 for 64-col tiles (+8 pad) — ldmatrix conflict-free
#define SCALE 0.03125f

typedef __nv_bfloat16 bf16;

// ----------------- scratch -----------------
__device__ bf16 g_xh[Mm * Ee],      g_xl[Mm * Ee];
__device__ bf16 g_Wqkh[Hh * 128 * Ee], g_Wqkl[Hh * 128 * Ee];
__device__ bf16 g_Woh[Ee * Ee],     g_Wol[Ee * Ee];
__device__ bf16 g_Qh[BH * Ss * Dd], g_Ql[BH * Ss * Dd];
__device__ bf16 g_Kh[BH * Ss * Dd], g_Kl[BH * Ss * Dd];
__device__ bf16 g_VTh[BH * Dd * Ss], g_VTl[BH * Dd * Ss];
__device__ bf16 g_AOh[Mm * Ee],     g_AOl[Mm * Ee];
__device__ float g_rZ[BH * Ss];

// ----------------- helpers -----------------
__device__ __forceinline__ uint32_t smem_u32(const void* p) {
    uint32_t a;
    asm("{ .reg .u64 t; cvta.to.shared.u64 t, %1; cvt.u32.u64 %0, t; }" : "=r"(a) : "l"(p));
    return a;
}
__device__ __forceinline__ uint32_t pk2f(float a, float b) {
    bf16 x = __float2bfloat16(a), y = __float2bfloat16(b);
    return (uint32_t)*(uint16_t*)&x | ((uint32_t)*(uint16_t*)&y << 16);
}
__device__ __forceinline__ void splitst(bf16* hp, bf16* lp, float4 v) {
    bf16 hx = __float2bfloat16(v.x), hy = __float2bfloat16(v.y);
    bf16 hz = __float2bfloat16(v.z), hw = __float2bfloat16(v.w);
    *(uint32_t*)hp       = (uint32_t)*(uint16_t*)&hx | ((uint32_t)*(uint16_t*)&hy << 16);
    *(uint32_t*)(hp + 2) = (uint32_t)*(uint16_t*)&hz | ((uint32_t)*(uint16_t*)&hw << 16);
    *(uint32_t*)lp       = pk2f(v.x - __bfloat162float(hx), v.y - __bfloat162float(hy));
    *(uint32_t*)(lp + 2) = pk2f(v.z - __bfloat162float(hz), v.w - __bfloat162float(hw));
}
__device__ __forceinline__ void wr_split(bf16* oh, bf16* ol, size_t idx, float a, float b) {
    bf16 ha = __float2bfloat16(a), hb = __float2bfloat16(b);
    *(uint32_t*)(oh + idx) = (uint32_t)*(uint16_t*)&ha | ((uint32_t)*(uint16_t*)&hb << 16);
    *(uint32_t*)(ol + idx) = pk2f(a - __bfloat162float(ha), b - __bfloat162float(hb));
}
__device__ __forceinline__ void mma16816(float* c, const uint32_t a[4], uint32_t b0, uint32_t b1) {
    asm volatile("mma.sync.aligned.m16n8k16.row.col.f32.bf16.bf16.f32 "
                 "{%0,%1,%2,%3}, {%4,%5,%6,%7}, {%8,%9}, {%0,%1,%2,%3};"
                 : "+f"(c[0]), "+f"(c[1]), "+f"(c[2]), "+f"(c[3])
                 : "r"(a[0]), "r"(a[1]), "r"(a[2]), "r"(a[3]), "r"(b0), "r"(b1));
}
__device__ __forceinline__ void ldsm4(uint32_t addr, uint32_t* r) {
    asm volatile("ldmatrix.sync.aligned.m8n8.x4.shared.b16 {%0,%1,%2,%3}, [%4];"
                 : "=r"(r[0]), "=r"(r[1]), "=r"(r[2]), "=r"(r[3]) : "r"(addr));
}
__device__ __forceinline__ void cpasync16(uint32_t dst, const void* src) {
    asm volatile("cp.async.cg.shared.global [%0], [%1], 16;" :: "r"(dst), "l"(src));
}
__device__ __forceinline__ void cp_commit() { asm volatile("cp.async.commit_group;" ::: "memory"); }
template<int N> __device__ __forceinline__ void cp_wait() {
    asm volatile("cp.async.wait_group %0;" :: "n"(N) : "memory");
}
// ROWS x 32 bf16 (64B rows), stride SB.  256 threads.
template<int ROWS>
__device__ __forceinline__ void cp_r32(uint32_t sdst, const bf16* g, size_t ld, int t) {
#pragma unroll
    for (int i = 0; i < ROWS * 4 / 256; i++) {
        int c = i * 256 + t, row = c >> 2, cid = c & 3;
        cpasync16(sdst + row * (SB * 2) + cid * 16, g + (size_t)row * ld + cid * 8);
    }
}
// ROWS x 64 bf16 (128B rows), stride SQ.  256 threads.
template<int ROWS>
__device__ __forceinline__ void cp_r64(uint32_t sdst, const bf16* g, size_t ld, int t) {
#pragma unroll
    for (int i = 0; i < ROWS * 8 / 256; i++) {
        int c = i * 256 + t, row = c >> 3, cid = c & 7;
        cpasync16(sdst + row * (SQ * 2) + cid * 16, g + (size_t)row * ld + cid * 8);
    }
}
// 3-term split-bf16 tile MMA with ldmatrix fragment loads.
template<int SA_, int SBB, int MT, int NT, int KK>
__device__ __forceinline__ void mma_tile(uint32_t aH, uint32_t aL,
    uint32_t bH, uint32_t bL, int wm, int wn, int lane, float (*acc)[NT][4])
{
    const int ar  = (wm + (lane & 15)) * SA_ + ((lane >> 4) << 3);
    const int br0 = (wn + (lane & 7) + ((lane >> 4) << 3)) * SBB + (((lane >> 3) & 1) << 3);
#pragma unroll
    for (int ks = 0; ks < KK; ks += 16) {
        uint32_t ah[MT][4], al[MT][4];
#pragma unroll
        for (int mt = 0; mt < MT; mt++) {
            ldsm4(aH + (uint32_t)(ar + mt * 16 * SA_ + ks) * 2, ah[mt]);
            ldsm4(aL + (uint32_t)(ar + mt * 16 * SA_ + ks) * 2, al[mt]);
        }
        uint32_t bhv[NT][2], blv[NT][2];
#pragma unroll
        for (int np = 0; np < NT / 2; np++) {
            uint32_t r[4];
            ldsm4(bH + (uint32_t)(br0 + np * 16 * SBB + ks) * 2, r);
            bhv[2*np][0] = r[0]; bhv[2*np][1] = r[1];
            bhv[2*np+1][0] = r[2]; bhv[2*np+1][1] = r[3];
            ldsm4(bL + (uint32_t)(br0 + np * 16 * SBB + ks) * 2, r);
            blv[2*np][0] = r[0]; blv[2*np][1] = r[1];
            blv[2*np+1][0] = r[2]; blv[2*np+1][1] = r[3];
        }
#pragma unroll
        for (int nt = 0; nt < NT; nt++)
#pragma unroll
            for (int mt = 0; mt < MT; mt++) {
                mma16816(acc[mt][nt], ah[mt], bhv[nt][0], bhv[nt][1]);
                mma16816(acc[mt][nt], ah[mt], blv[nt][0], blv[nt][1]);
                mma16816(acc[mt][nt], al[mt], bhv[nt][0], bhv[nt][1]);
            }
    }
}
// 1-term (plain bf16, hh only) tile MMA — used only by k_stats (errors average in Z).
template<int SA_, int SBB, int MT, int NT, int KK>
__device__ __forceinline__ void mma1_tile(uint32_t aH, uint32_t bH,
    int wm, int wn, int lane, float (*acc)[NT][4])
{
    const int ar  = (wm + (lane & 15)) * SA_ + ((lane >> 4) << 3);
    const int br0 = (wn + (lane & 7) + ((lane >> 4) << 3)) * SBB + (((lane >> 3) & 1) << 3);
#pragma unroll
    for (int ks = 0; ks < KK; ks += 16) {
        uint32_t ah[MT][4];
#pragma unroll
        for (int mt = 0; mt < MT; mt++)
            ldsm4(aH + (uint32_t)(ar + mt * 16 * SA_ + ks) * 2, ah[mt]);
        uint32_t bhv[NT][2];
#pragma unroll
        for (int np = 0; np < NT / 2; np++) {
            uint32_t r[4];
            ldsm4(bH + (uint32_t)(br0 + np * 16 * SBB + ks) * 2, r);
            bhv[2*np][0] = r[0]; bhv[2*np][1] = r[1];
            bhv[2*np+1][0] = r[2]; bhv[2*np+1][1] = r[3];
        }
#pragma unroll
        for (int nt = 0; nt < NT; nt++)
#pragma unroll
            for (int mt = 0; mt < MT; mt++)
                mma16816(acc[mt][nt], ah[mt], bhv[nt][0], bhv[nt][1]);
    }
}

// ----------------- conversion / transpose kernels -----------------
__global__ void k_cvtx(const float* __restrict__ x) {
    int idx = blockIdx.x * 256 + threadIdx.x;
    float4 v = ((const float4*)x)[idx];
    splitst(g_xh + idx * 4, g_xl + idx * 4, v);
}
__global__ void k_trwf(const float* __restrict__ in, bf16* __restrict__ oh, bf16* __restrict__ ol,
                       int R, int C, size_t islab, size_t oslab, int row_off)
{
    __shared__ float tile[32][33];
    const float* I = in + (size_t)blockIdx.z * islab;
    int r0 = blockIdx.x << 5, c0 = blockIdx.y << 5;
    int tx = threadIdx.x, ty = threadIdx.y;
#pragma unroll
    for (int i = ty; i < 32; i += 8)
        tile[i][tx] = I[(size_t)(r0 + i) * C + c0 + tx];
    __syncthreads();
#pragma unroll
    for (int i = ty; i < 32; i += 8) {
        float v = tile[tx][i];
        bf16 h = __float2bfloat16(v);
        size_t o = (size_t)blockIdx.z * oslab + (size_t)(row_off + c0 + i) * R + r0 + tx;
        oh[o] = h;
        ol[o] = __float2bfloat16(v - __bfloat162float(h));
    }
}
// fused: VT[bh][d][s] = Q[bh][s][d] * rZ[bh][s], split hi/lo.  Runs AFTER k_stats.
__global__ void k_trqs()
{
    __shared__ bf16 th[32][33], tl[32][33];
    int bh = blockIdx.z, s0 = blockIdx.x << 5, d0 = blockIdx.y << 5;
    int tx = threadIdx.x, ty = threadIdx.y;
    const bf16* Ih = g_Qh + (size_t)bh * Ss * Dd;
    const bf16* Il = g_Ql + (size_t)bh * Ss * Dd;
#pragma unroll
    for (int i = ty; i < 32; i += 8) {
        th[i][tx] = Ih[(size_t)(s0 + i) * Dd + d0 + tx];
        tl[i][tx] = Il[(size_t)(s0 + i) * Dd + d0 + tx];
    }
    __syncthreads();
    float rz = g_rZ[bh * Ss + s0 + tx];
#pragma unroll
    for (int i = ty; i < 32; i += 8) {
        float v = (__bfloat162float(th[tx][i]) + __bfloat162float(tl[tx][i])) * rz;
        bf16 h = __float2bfloat16(v);
        size_t o = (size_t)bh * Dd * Ss + (size_t)(d0 + i) * Ss + s0 + tx;
        g_VTh[o] = h;
        g_VTl[o] = __float2bfloat16(v - __bfloat162float(h));
    }
}

// ============================================================================
// k_proj: 128m x 64n tile of [Q|K] = x @ Wqk^T + bias.  grid (32,32), 256 thr.
// Single sync per chunk: wait -> sync -> issue-next -> mma.
// ============================================================================
__global__ __launch_bounds__(256, 3) void k_proj(const float* __restrict__ bq,
                                                 const float* __restrict__ bk)
{
    extern __shared__ char sm[];
    const int t = threadIdx.x, lane = t & 31, wid = t >> 5;
    const int wm = (wid >> 1) * 32, wn = (wid & 1) * 32;
    const int m0 = blockIdx.x << 7, h = blockIdx.y >> 1, nh = blockIdx.y & 1;
    uint32_t sb = smem_u32(sm);
    const bf16* Ahg = g_xh + (size_t)m0 * Ee;
    const bf16* Alg = g_xl + (size_t)m0 * Ee;
    const bf16* Bhg = g_Wqkh + ((size_t)h * 128 + nh * 64) * Ee;
    const bf16* Blg = g_Wqkl + ((size_t)h * 128 + nh * 64) * Ee;

    float acc[2][4][4];
#pragma unroll
    for (int i = 0; i < 2; i++)
#pragma unroll
        for (int j = 0; j < 4; j++)
#pragma unroll
            for (int v = 0; v < 4; v++) acc[i][j][v] = 0.f;

    cp_r32<128>(sb + 0,     Ahg, Ee, t);
    cp_r32<128>(sb + 10240, Alg, Ee, t);
    cp_r32<64> (sb + 20480, Bhg, Ee, t);
    cp_r32<64> (sb + 25600, Blg, Ee, t);
    cp_commit();
    for (int c = 0; c < 32; c++) {
        cp_wait<0>();
        __syncthreads();
        if (c < 31) {
            int k0 = (c + 1) * 32;
            uint32_t nb = sb + ((c + 1) & 1) * 30720u;
            cp_r32<128>(nb + 0,     Ahg + k0, Ee, t);
            cp_r32<128>(nb + 10240, Alg + k0, Ee, t);
            cp_r32<64> (nb + 20480, Bhg + k0, Ee, t);
            cp_r32<64> (nb + 25600, Blg + k0, Ee, t);
            cp_commit();
        }
        uint32_t ab = sb + (c & 1) * 30720u;
        mma_tile<SB, SB, 2, 4, 32>(ab, ab + 10240, ab + 20480, ab + 25600, wm, wn, lane, acc);
    }

    const int b = m0 >> 10, hb = b * Hh + h;
    const bool isQ = (nh == 0);
    bf16* dh = isQ ? g_Qh : g_Kh;
    bf16* dl = isQ ? g_Ql : g_Kl;
    const float* bias = (isQ ? bq : bk) + h * Dd;
    const int gr = lane >> 2, tc = (lane & 3) * 2;
#pragma unroll
    for (int mt = 0; mt < 2; mt++)
#pragma unroll
        for (int nt = 0; nt < 4; nt++) {
            int d = wn + nt * 8 + tc;
            float bx = bias[d], by = bias[d + 1];
            int s = (m0 & 1023) + wm + mt * 16 + gr;
            wr_split(dh, dl, ((size_t)hb * Ss + s) * Dd + d,
                     acc[mt][nt][0] + bx, acc[mt][nt][1] + by);
            wr_split(dh, dl, ((size_t)hb * Ss + s + 8) * Dd + d,
                     acc[mt][nt][2] + bx, acc[mt][nt][3] + by);
        }
}

// ============================================================================
// k_stats: Z[k] = sum_q exp(S_qk), S = QK^T/32.  1-term plain-bf16 MMA —
// per-q errors are independent and average out in the positive sum Z.
// grid (16 k-tiles, 64 bh), 256 thr.  smem: Q stages 0/18432, K 36864, rz 46080.
// ============================================================================
__global__ __launch_bounds__(256, 3) void k_stats()
{
    extern __shared__ char sm[];
    const int t = threadIdx.x, lane = t & 31, wid = t >> 5;
    const int wm = (wid >> 1) * 32, wn = (wid & 1) * 32;
    const int k0 = blockIdx.x << 6, bh = blockIdx.y;
    const int tc = (lane & 3) * 2;
    uint32_t sb = smem_u32(sm);
    const bf16* Qhg = g_Qh + (size_t)bh * Ss * Dd;

    cp_r64<64>(sb + 36864, g_Kh + ((size_t)bh * Ss + k0) * Dd, Dd, t);
    cp_r64<128>(sb + 0, Qhg, Dd, t);
    cp_commit();

    float zs[4][2];
#pragma unroll
    for (int i = 0; i < 4; i++) { zs[i][0] = 0.f; zs[i][1] = 0.f; }

    for (int c = 0; c < 8; c++) {
        cp_wait<0>();
        __syncthreads();
        if (c < 7) {
            size_t q1 = (size_t)(c + 1) * 128;
            cp_r64<128>(sb + ((c + 1) & 1) * 18432u, Qhg + q1 * Dd, Dd, t);
            cp_commit();
        }
        float acc[2][4][4];
#pragma unroll
        for (int i = 0; i < 2; i++)
#pragma unroll
            for (int j = 0; j < 4; j++)
#pragma unroll
                for (int v = 0; v < 4; v++) acc[i][j][v] = 0.f;
        mma1_tile<SQ, SQ, 2, 4, 64>(sb + (c & 1) * 18432u, sb + 36864, wm, wn, lane, acc);
#pragma unroll
        for (int mt = 0; mt < 2; mt++)
#pragma unroll
            for (int nt = 0; nt < 4; nt++) {
                zs[nt][0] += __expf(acc[mt][nt][0] * SCALE) + __expf(acc[mt][nt][2] * SCALE);
                zs[nt][1] += __expf(acc[mt][nt][1] * SCALE) + __expf(acc[mt][nt][3] * SCALE);
            }
    }
#pragma unroll
    for (int nt = 0; nt < 4; nt++)
#pragma unroll
        for (int j = 0; j < 2; j++)
#pragma unroll
            for (int o = 4; o <= 16; o <<= 1) {
                zs[nt][j] += __shfl_xor_sync(0xFFFFFFFFu, zs[nt][j], o);
            }
    float* rz = (float*)(sm + 46080);
    __syncthreads();
    if (lane < 4) {
        int qw = wid >> 1;
#pragma unroll
        for (int nt = 0; nt < 4; nt++) {
            int col = wn + nt * 8 + tc;
            rz[qw * 64 + col]     = zs[nt][0];
            rz[qw * 64 + col + 1] = zs[nt][1];
        }
    }
    __syncthreads();
    if (t < 64) {
        float Z = rz[t] + rz[64 + t] + rz[128 + t] + rz[192 + t];
        g_rZ[bh * Ss + k0 + t] = 1.0f / Z;
    }
}

// ============================================================================
// k_avf: fused AO = exp(QK^T/32) @ (rZ⊙V).  grid (8, 64), 256 thr.
// smem map (99328 B total):
//   [0, 36864)      Q prologue (hi 18432 | lo 18432), dead after fragment hoist
//   [0, 40960)      P double buffer after hoist: pb*20480 {hi 10240 | lo 10240}
//   [40960, 68608)  K 3 stages: 40960 + s*9216 {hi 4608 | lo 4608}
//   [68608, 99328)  V 3 stages: 68608 + s*10240 {hi 5120 | lo 5120}
// ============================================================================
__global__ __launch_bounds__(256, 2) void k_avf()
{
    extern __shared__ char sm[];
    const int t = threadIdx.x, lane = t & 31, wid = t >> 5;
    const int wm1 = wid * 16;
    const int wm2 = (wid >> 1) * 32, wn2 = (wid & 1) * 32;
    const int q0 = blockIdx.x << 7, bh = blockIdx.y;
    const int gr = lane >> 2, tc = (lane & 3) * 2;
    uint32_t sb = smem_u32(sm);
    const bf16* Khg = g_Kh + (size_t)bh * Ss * Dd;
    const bf16* Klg = g_Kl + (size_t)bh * Ss * Dd;
    const bf16* Vhg = g_VTh + (size_t)bh * Dd * Ss;
    const bf16* Vlg = g_VTl + (size_t)bh * Dd * Ss;

    cp_r64<128>(sb + 0,     g_Qh + ((size_t)bh * Ss + q0) * Dd, Dd, t);
    cp_r64<128>(sb + 18432, g_Ql + ((size_t)bh * Ss + q0) * Dd, Dd, t);
    cp_r64<32>(sb + 40960, Khg, Dd, t);
    cp_r64<32>(sb + 45568, Klg, Dd, t);
    cp_r32<64>(sb + 68608, Vhg, Ss, t);
    cp_r32<64>(sb + 73728, Vlg, Ss, t);
    cp_commit();

    float acc2[2][4][4];
#pragma unroll
    for (int i = 0; i < 2; i++)
#pragma unroll
        for (int j = 0; j < 4; j++)
#pragma unroll
            for (int v = 0; v < 4; v++) acc2[i][j][v] = 0.f;

    const int ar1 = (wm1 + (lane & 15)) * SQ + ((lane >> 4) << 3);
    const int br1 = ((lane & 7) + ((lane >> 4) << 3)) * SQ + (((lane >> 3) & 1) << 3);
    uint32_t qh[4][4], ql[4][4];

    for (int c = 0; c < 32; c++) {
        int st = c % 3;
        if (c < 31) {
            int k1 = (c + 1) * 32, sn = (c + 1) % 3;
            uint32_t kb = sb + 40960 + sn * 9216u;
            uint32_t vb = sb + 68608 + sn * 10240u;
            cp_r64<32>(kb,        Khg + (size_t)k1 * Dd, Dd, t);
            cp_r64<32>(kb + 4608, Klg + (size_t)k1 * Dd, Dd, t);
            cp_r32<64>(vb,        Vhg + k1, Ss, t);
            cp_r32<64>(vb + 5120, Vlg + k1, Ss, t);
            cp_commit();
            cp_wait<1>();
        } else cp_wait<0>();
        __syncthreads();
        if (c == 0) {   // hoist Q fragments (chunk-invariant); Q smem dead afterwards
#pragma unroll
            for (int i = 0; i < 4; i++) {
                ldsm4(sb + (uint32_t)(ar1 + i * 16) * 2, qh[i]);
                ldsm4(sb + 18432 + (uint32_t)(ar1 + i * 16) * 2, ql[i]);
            }
            __syncthreads();   // no warp may write P (aliased over Q) before all preload
        }
        // MMA#1: S chunk (128q x 32k), warp tile 16q x 32k, Q from registers
        float acc1[4][4];
#pragma unroll
        for (int j = 0; j < 4; j++)
#pragma unroll
            for (int v = 0; v < 4; v++) acc1[j][v] = 0.f;
        uint32_t kb2 = sb + 40960 + st * 9216u;
#pragma unroll
        for (int i = 0; i < 4; i++) {
            int ks = i * 16;
            uint32_t bhv[4][2], blv[4][2];
#pragma unroll
            for (int np = 0; np < 2; np++) {
                uint32_t r[4];
                ldsm4(kb2 + (uint32_t)(br1 + np * 16 * SQ + ks) * 2, r);
                bhv[2*np][0] = r[0]; bhv[2*np][1] = r[1];
                bhv[2*np+1][0] = r[2]; bhv[2*np+1][1] = r[3];
                ldsm4(kb2 + 4608 + (uint32_t)(br1 + np * 16 * SQ + ks) * 2, r);
                blv[2*np][0] = r[0]; blv[2*np][1] = r[1];
                blv[2*np+1][0] = r[2]; blv[2*np+1][1] = r[3];
            }
#pragma unroll
            for (int nt = 0; nt < 4; nt++) {
                mma16816(acc1[nt], qh[i], bhv[nt][0], bhv[nt][1]);
                mma16816(acc1[nt], qh[i], blv[nt][0], blv[nt][1]);
                mma16816(acc1[nt], ql[i], bhv[nt][0], bhv[nt][1]);
            }
        }
        // exp + split -> P[pb]  (rZ already folded into V)
        int pb = c & 1;
        bf16* Ph = (bf16*)(sm + pb * 20480);
        bf16* Pl = (bf16*)(sm + pb * 20480 + 10240);
#pragma unroll
        for (int nt = 0; nt < 4; nt++) {
            int col = nt * 8 + tc;
            float p0 = __expf(acc1[nt][0] * SCALE);
            float p1 = __expf(acc1[nt][1] * SCALE);
            float p2 = __expf(acc1[nt][2] * SCALE);
            float p3 = __expf(acc1[nt][3] * SCALE);
            wr_split(Ph, Pl, (size_t)(wm1 + gr) * SB + col, p0, p1);
            wr_split(Ph, Pl, (size_t)(wm1 + gr + 8) * SB + col, p2, p3);
        }
        __syncthreads();
        // MMA#2: acc2 += P @ V'  (warp tile 32q x 32d); no trailing sync (P double-buffered,
        // K/V triple-buffered => next chunk's writes never touch buffers still being read)
        uint32_t vb2 = sb + 68608 + st * 10240u;
        mma_tile<SB, SB, 2, 4, 32>(sb + pb * 20480u, sb + pb * 20480u + 10240, vb2, vb2 + 5120,
                                   wm2, wn2, lane, acc2);
    }

    const int b = bh >> 4, h = bh & 15;
#pragma unroll
    for (int mt = 0; mt < 2; mt++)
#pragma unroll
        for (int nt = 0; nt < 4; nt++) {
            int q = q0 + wm2 + mt * 16 + gr, d = wn2 + nt * 8 + tc;
            wr_split(g_AOh, g_AOl, ((size_t)b * Ss + q) * Ee + h * Dd + d,
                     acc2[mt][nt][0], acc2[mt][nt][1]);
            wr_split(g_AOh, g_AOl, ((size_t)b * Ss + q + 8) * Ee + h * Dd + d,
                     acc2[mt][nt][2], acc2[mt][nt][3]);
        }
}

// ============================================================================
// k_oproj: out(128m x 64n) = AO @ Wo + bo.  grid (32, 16), 256 thr.
// Single sync per chunk.
// ============================================================================
__global__ __launch_bounds__(256, 3) void k_oproj(const float* __restrict__ bo,
                                                  float* __restrict__ out)
{
    extern __shared__ char sm[];
    const int t = threadIdx.x, lane = t & 31, wid = t >> 5;
    const int wm = (wid >> 1) * 32, wn = (wid & 1) * 32;
    const int m0 = blockIdx.x << 7, n0 = blockIdx.y << 6;
    uint32_t sb = smem_u32(sm);
    const bf16* Ahg = g_AOh + (size_t)m0 * Ee;
    const bf16* Alg = g_AOl + (size_t)m0 * Ee;
    const bf16* Bhg = g_Woh + (size_t)n0 * Ee;
    const bf16* Blg = g_Wol + (size_t)n0 * Ee;

    float acc[2][4][4];
#pragma unroll
    for (int i = 0; i < 2; i++)
#pragma unroll
        for (int j = 0; j < 4; j++)
#pragma unroll
            for (int v = 0; v < 4; v++) acc[i][j][v] = 0.f;

    cp_r32<128>(sb + 0,     Ahg, Ee, t);
    cp_r32<128>(sb + 10240, Alg, Ee, t);
    cp_r32<64> (sb + 20480, Bhg, Ee, t);
    cp_r32<64> (sb + 25600, Blg, Ee, t);
    cp_commit();
    for (int c = 0; c < 32; c++) {
        cp_wait<0>();
        __syncthreads();
        if (c < 31) {
            int k0 = (c + 1) * 32;
            uint32_t nb = sb + ((c + 1) & 1) * 30720u;
            cp_r32<128>(nb + 0,     Ahg + k0, Ee, t);
            cp_r32<128>(nb + 10240, Alg + k0, Ee, t);
            cp_r32<64> (nb + 20480, Bhg + k0, Ee, t);
            cp_r32<64> (nb + 25600, Blg + k0, Ee, t);
            cp_commit();
        }
        uint32_t ab = sb + (c & 1) * 30720u;
        mma_tile<SB, SB, 2, 4, 32>(ab, ab + 10240, ab + 20480, ab + 25600, wm, wn, lane, acc);
    }

    const int gr = lane >> 2, tc = (lane & 3) * 2;
#pragma unroll
    for (int mt = 0; mt < 2; mt++)
#pragma unroll
        for (int nt = 0; nt < 4; nt++) {
            int m = m0 + wm + mt * 16 + gr, n = n0 + wn + nt * 8 + tc;
            float bx = bo[n], by = bo[n + 1];
            *(float2*)(out + (size_t)m * Ee + n) =
                make_float2(acc[mt][nt][0] + bx, acc[mt][nt][1] + by);
            *(float2*)(out + (size_t)(m + 8) * Ee + n) =
                make_float2(acc[mt][nt][2] + bx, acc[mt][nt][3] + by);
        }
}

// ============================================================================
extern "C" void kernel_launch(void* const* d_in, const int* in_sizes, int n_in,
                              void* d_out, int out_size)
{
    const float* x  = (const float*)d_in[0];
    const float* Wq = (const float*)d_in[1];
    const float* bq = (const float*)d_in[2];
    const float* Wk = (const float*)d_in[3];
    const float* bk = (const float*)d_in[4];
    // d_in[5], d_in[6] (W_v, b_v) intentionally unused: reference bug v = q
    const float* Wo = (const float*)d_in[7];
    const float* bo = (const float*)d_in[8];
    float* out = (float*)d_out;

    cudaFuncSetAttribute(k_proj,  cudaFuncAttributeMaxDynamicSharedMemorySize, 61440);
    cudaFuncSetAttribute(k_stats, cudaFuncAttributeMaxDynamicSharedMemorySize, 47104);
    cudaFuncSetAttribute(k_avf,   cudaFuncAttributeMaxDynamicSharedMemorySize, 99328);
    cudaFuncSetAttribute(k_oproj, cudaFuncAttributeMaxDynamicSharedMemorySize, 61440);

    bf16 *Wqkh, *Wqkl, *Woh, *Wol;
    cudaGetSymbolAddress((void**)&Wqkh, g_Wqkh);
    cudaGetSymbolAddress((void**)&Wqkl, g_Wqkl);
    cudaGetSymbolAddress((void**)&Woh,  g_Woh);
    cudaGetSymbolAddress((void**)&Wol,  g_Wol);

    dim3 tb8(32, 8);
    k_cvtx<<<4096, 256>>>(x);
    k_trwf<<<dim3(32, 2, 16), tb8>>>(Wq, Wqkh, Wqkl, Ee, Dd, (size_t)Ee * Dd, 128 * Ee, 0);
    k_trwf<<<dim3(32, 2, 16), tb8>>>(Wk, Wqkh, Wqkl, Ee, Dd, (size_t)Ee * Dd, 128 * Ee, 64);
    k_trwf<<<dim3(32, 32, 1), tb8>>>(Wo, Woh, Wol, Ee, Ee, (size_t)Ee * Ee, (size_t)Ee * Ee, 0);

    k_proj <<<dim3(Mm / 128, Hh * 2), 256, 61440>>>(bq, bk);
    k_stats<<<dim3(Ss / 64, BH), 256, 47104>>>();
    k_trqs <<<dim3(32, 2, BH), tb8>>>();
    k_avf  <<<dim3(Ss / 128, BH), 256, 99328>>>();
    k_oproj<<<dim3(Mm / 128, Ee / 64), 256, 61440>>>(bo, out);
}